// round 2
// baseline (speedup 1.0000x reference)
#include <cuda_runtime.h>
#include <math.h>

#define NN 64
#define MATSZ 4096
#define NB 4096
#define PAD 65
#define NSWEEPS 8

enum { F_NONE = -1, F_SQRT = 0, F_INVSQRT = 1, F_LOG = 2, F_EXP = 3 };

// device-global scratch (no runtime allocation allowed)
__device__ float  g_bufA[(size_t)NB * MATSZ];
__device__ float  g_bufB[(size_t)NB * MATSZ];
__device__ float  g_bufC[(size_t)NB * MATSZ];
__device__ float  g_bufD[(size_t)NB * MATSZ];
__device__ float  g_small[20 * MATSZ];
__device__ double g_part[256];
__device__ float  g_scal[4];

__device__ __forceinline__ float apply_fn(int f, float w) {
    switch (f) {
        case F_SQRT:    return sqrtf(fmaxf(w, 0.0f));
        case F_INVSQRT: return rsqrtf(fmaxf(w, 1e-30f));
        case F_LOG:     return logf(fmaxf(w, 1e-30f));
        case F_EXP:     return expf(w);
    }
    return w;
}

// ---------------------------------------------------------------------------
// Batched symmetric Jacobi eigensolver + fused matrix-function reconstruction.
// One 64x64 matrix per 256-thread block. Fixed sweeps (deterministic).
// Round-robin pairing round r: (63, r); k=1..31: ((r+k)%63, (r+63-k)%63).
// out1 = V f1(L) V^T ; if f2 != F_NONE also out2 = V f2(L) V^T.
// ---------------------------------------------------------------------------
__global__ __launch_bounds__(256) void jacobi_kernel(
    const float* __restrict__ in, float* __restrict__ out1,
    float* __restrict__ out2, int f1, int f2)
{
    __shared__ float As[NN * PAD];
    __shared__ float Vs[NN * PAD];
    __shared__ float carr[32], sarr[32];
    __shared__ float wv[NN], fw[NN];

    const int tid = threadIdx.x;
    const size_t boff = (size_t)blockIdx.x * MATSZ;

    for (int idx = tid; idx < MATSZ; idx += 256) {
        int i = idx >> 6, j = idx & 63;
        As[i * PAD + j] = in[boff + idx];
        Vs[i * PAD + j] = (i == j) ? 1.0f : 0.0f;
    }

    for (int sw = 0; sw < NSWEEPS; ++sw) {
        for (int r = 0; r < 63; ++r) {
            __syncthreads();
            if (tid < 32) {
                int p, q;
                if (tid == 0) { p = 63; q = r; }
                else          { p = (r + tid) % 63; q = (r + 63 - tid) % 63; }
                float app = As[p * PAD + p], aqq = As[q * PAD + q];
                float apq = As[p * PAD + q];
                float c = 1.0f, s = 0.0f;
                if (fabsf(apq) > 0.0f) {
                    float tau = (aqq - app) / (2.0f * apq);
                    float t = 1.0f / (fabsf(tau) + sqrtf(1.0f + tau * tau));
                    if (tau < 0.0f) t = -t;
                    c = rsqrtf(1.0f + t * t);
                    s = t * c;
                }
                carr[tid] = c; sarr[tid] = s;
            }
            __syncthreads();
            // row phase: A <- J^T A   (2048 work items)
            #pragma unroll
            for (int it = 0; it < 8; ++it) {
                int fidx = tid + it * 256;
                int pr = fidx >> 6, j = fidx & 63;
                int p, q;
                if (pr == 0) { p = 63; q = r; }
                else         { p = (r + pr) % 63; q = (r + 63 - pr) % 63; }
                float c = carr[pr], s = sarr[pr];
                float ap = As[p * PAD + j], aq = As[q * PAD + j];
                As[p * PAD + j] = c * ap - s * aq;
                As[q * PAD + j] = s * ap + c * aq;
            }
            __syncthreads();
            // col phase: A <- A J and V <- V J   (4096 work items)
            #pragma unroll
            for (int it = 0; it < 16; ++it) {
                int fidx = tid + it * 256;
                int pr = (fidx >> 6) & 31, i = fidx & 63;
                int p, q;
                if (pr == 0) { p = 63; q = r; }
                else         { p = (r + pr) % 63; q = (r + 63 - pr) % 63; }
                float c = carr[pr], s = sarr[pr];
                float* Mp = (fidx < 2048) ? As : Vs;
                float mp = Mp[i * PAD + p], mq = Mp[i * PAD + q];
                Mp[i * PAD + p] = c * mp - s * mq;
                Mp[i * PAD + q] = s * mp + c * mq;
            }
        }
    }
    __syncthreads();

    if (tid < 64) {
        float w = As[tid * PAD + tid];
        wv[tid] = w;
        fw[tid] = apply_fn(f1, w);
    }
    __syncthreads();
    for (int idx = tid; idx < MATSZ; idx += 256) {
        int i = idx >> 6, k = idx & 63;
        As[i * PAD + k] = Vs[i * PAD + k] * fw[k];
    }
    __syncthreads();
    for (int idx = tid; idx < MATSZ; idx += 256) {
        int i = idx >> 6, j = idx & 63;
        float acc = 0.0f;
        #pragma unroll
        for (int k = 0; k < 64; ++k) acc += As[i * PAD + k] * Vs[j * PAD + k];
        out1[boff + idx] = acc;
    }
    if (f2 != F_NONE) {
        __syncthreads();
        if (tid < 64) fw[tid] = apply_fn(f2, wv[tid]);
        __syncthreads();
        for (int idx = tid; idx < MATSZ; idx += 256) {
            int i = idx >> 6, k = idx & 63;
            As[i * PAD + k] = Vs[i * PAD + k] * fw[k];
        }
        __syncthreads();
        for (int idx = tid; idx < MATSZ; idx += 256) {
            int i = idx >> 6, j = idx & 63;
            float acc = 0.0f;
            #pragma unroll
            for (int k = 0; k < 64; ++k) acc += As[i * PAD + k] * Vs[j * PAD + k];
            out2[boff + idx] = acc;
        }
    }
}

// 4x4 register tile inner product: C[ti..][tj..] += op(A) op(B)
template <int TA, int TB>
__device__ __forceinline__ void tile_mm(const float* __restrict__ A,
                                        const float* __restrict__ B,
                                        float acc[4][4], int ti, int tj)
{
    #pragma unroll 4
    for (int k = 0; k < 64; ++k) {
        float a[4], b[4];
        #pragma unroll
        for (int r = 0; r < 4; ++r) a[r] = TA ? A[k * 64 + ti + r] : A[(ti + r) * 64 + k];
        #pragma unroll
        for (int c = 0; c < 4; ++c) b[c] = TB ? B[(tj + c) * 64 + k] : B[k * 64 + tj + c];
        #pragma unroll
        for (int r = 0; r < 4; ++r)
            #pragma unroll
            for (int c = 0; c < 4; ++c) acc[r][c] += a[r] * b[c];
    }
}

// out_b = scale * L @ X_b @ op(R)  (L, R broadcast; 48KB smem, Ts reuses Xs)
__global__ __launch_bounds__(256) void cong_kernel(
    const float* __restrict__ Lm, const float* __restrict__ Xb,
    const float* __restrict__ Rm, float* __restrict__ out,
    int useScale, int transR)
{
    __shared__ float Ls[MATSZ], Rs[MATSZ], Xs[MATSZ];
    const int tid = threadIdx.x;
    const size_t boff = (size_t)blockIdx.x * MATSZ;
    for (int i = tid; i < MATSZ; i += 256) {
        Ls[i] = Lm[i]; Rs[i] = Rm[i]; Xs[i] = Xb[boff + i];
    }
    __syncthreads();

    const int ti = (tid >> 4) << 2, tj = (tid & 15) << 2;
    float acc[4][4] = {};
    tile_mm<0, 0>(Ls, Xs, acc, ti, tj);       // T = L @ X
    __syncthreads();                          // all reads of Xs done
    #pragma unroll
    for (int r = 0; r < 4; ++r)
        #pragma unroll
        for (int c = 0; c < 4; ++c) Xs[(ti + r) * 64 + tj + c] = acc[r][c];
    __syncthreads();

    float sc = useScale ? g_scal[0] : 1.0f;
    float acc2[4][4] = {};
    if (transR) tile_mm<0, 1>(Xs, Rs, acc2, ti, tj);
    else        tile_mm<0, 0>(Xs, Rs, acc2, ti, tj);
    #pragma unroll
    for (int r = 0; r < 4; ++r) {
        float4 v = make_float4(acc2[r][0] * sc, acc2[r][1] * sc,
                               acc2[r][2] * sc, acc2[r][3] * sc);
        *reinterpret_cast<float4*>(out + boff + (size_t)(ti + r) * 64 + tj) = v;
    }
}

// out_b = A_b @ B_(b*strideB)   (strideB = 0 broadcasts B)
__global__ __launch_bounds__(256) void gemmB_kernel(
    const float* __restrict__ A, const float* __restrict__ Bm, int strideB,
    float* __restrict__ out)
{
    __shared__ float As_[MATSZ], Bs_[MATSZ];
    const int tid = threadIdx.x;
    const size_t boff = (size_t)blockIdx.x * MATSZ;
    const float* Bb = Bm + (size_t)blockIdx.x * strideB;
    for (int i = tid; i < MATSZ; i += 256) { As_[i] = A[boff + i]; Bs_[i] = Bb[i]; }
    __syncthreads();
    const int ti = (tid >> 4) << 2, tj = (tid & 15) << 2;
    float acc[4][4] = {};
    tile_mm<0, 0>(As_, Bs_, acc, ti, tj);
    #pragma unroll
    for (int r = 0; r < 4; ++r) {
        float4 v = make_float4(acc[r][0], acc[r][1], acc[r][2], acc[r][3]);
        *reinterpret_cast<float4*>(out + boff + (size_t)(ti + r) * 64 + tj) = v;
    }
}

// single 64x64 gemm: C = op(A) @ B
__global__ __launch_bounds__(256) void gemm1_kernel(
    const float* __restrict__ A, const float* __restrict__ B,
    float* __restrict__ C, int transA)
{
    __shared__ float As_[MATSZ], Bs_[MATSZ];
    const int tid = threadIdx.x;
    for (int i = tid; i < MATSZ; i += 256) { As_[i] = A[i]; Bs_[i] = B[i]; }
    __syncthreads();
    const int ti = (tid >> 4) << 2, tj = (tid & 15) << 2;
    float acc[4][4] = {};
    if (transA) tile_mm<1, 0>(As_, Bs_, acc, ti, tj);
    else        tile_mm<0, 0>(As_, Bs_, acc, ti, tj);
    #pragma unroll
    for (int r = 0; r < 4; ++r) {
        float4 v = make_float4(acc[r][0], acc[r][1], acc[r][2], acc[r][3]);
        *reinterpret_cast<float4*>(C + (size_t)(ti + r) * 64 + tj) = v;
    }
}

// out[e] = mean_b in[b*4096 + e]   (grid 16 x 256, deterministic order)
__global__ void mean_kernel(const float* __restrict__ in, float* __restrict__ out)
{
    int e = blockIdx.x * blockDim.x + threadIdx.x;
    double a0 = 0, a1 = 0, a2 = 0, a3 = 0;
    for (int b = 0; b < NB; b += 4) {
        a0 += (double)in[(size_t)(b + 0) * MATSZ + e];
        a1 += (double)in[(size_t)(b + 1) * MATSZ + e];
        a2 += (double)in[(size_t)(b + 2) * MATSZ + e];
        a3 += (double)in[(size_t)(b + 3) * MATSZ + e];
    }
    out[e] = (float)((a0 + a1 + a2 + a3) * (1.0 / (double)NB));
}

// deterministic two-pass sum of squares: 256 blocks x 65536-element chunks
__global__ __launch_bounds__(256) void sumsq_kernel(const float* __restrict__ in)
{
    __shared__ double sh[256];
    const int tid = threadIdx.x;
    const size_t base = (size_t)blockIdx.x * 65536;
    double a = 0;
    for (int i = tid; i < 65536; i += 256) {
        float v = in[base + i];
        a += (double)v * (double)v;
    }
    sh[tid] = a;
    __syncthreads();
    for (int s = 128; s > 0; s >>= 1) {
        if (tid < s) sh[tid] += sh[tid + s];
        __syncthreads();
    }
    if (tid == 0) g_part[blockIdx.x] = sh[0];
}

__global__ void finalize_kernel(const float* __restrict__ shift)
{
    __shared__ double sh[256];
    const int tid = threadIdx.x;
    sh[tid] = g_part[tid];
    __syncthreads();
    for (int s = 128; s > 0; s >>= 1) {
        if (tid < s) sh[tid] += sh[tid + s];
        __syncthreads();
    }
    if (tid == 0) {
        double var = sh[0] / (double)NB;
        g_scal[0] = shift[0] / (float)sqrt(var + 1e-5);
    }
}

extern "C" void kernel_launch(void* const* d_in, const int* in_sizes, int n_in,
                              void* d_out, int out_size)
{
    const float* X     = (const float*)d_in[0];
    const float* W     = (const float*)d_in[1];
    const float* M     = (const float*)d_in[2];
    const float* shift = (const float*)d_in[3];
    float* out = (float*)d_out;

    float *bufA, *bufB, *bufC, *bufD, *sm;
    cudaGetSymbolAddress((void**)&bufA, g_bufA);
    cudaGetSymbolAddress((void**)&bufB, g_bufB);
    cudaGetSymbolAddress((void**)&bufC, g_bufC);
    cudaGetSymbolAddress((void**)&bufD, g_bufD);
    cudaGetSymbolAddress((void**)&sm,   g_small);
    #define SLOT(i) (sm + (i) * MATSZ)
    // slots: 0 Mh, 1 Mnh, 2 Wh, 3 tmp, 4 Wc, 5 Wch, 6 Wcnh, 7 P, 8 Q, 9 R,
    //        10 G0, 11 G0h, 12 G0nh, 13 Tm, 14 expTm, 15 G, 16 mnh

    // parameter prep (tiny single-matrix ops)
    jacobi_kernel<<<1, 256>>>(M, SLOT(0), SLOT(1), F_SQRT, F_INVSQRT);      // Mh, Mnh
    jacobi_kernel<<<1, 256>>>(W, SLOT(2), SLOT(2), F_SQRT, F_NONE);         // Wh (== Wp)
    gemm1_kernel<<<1, 256>>>(SLOT(1), SLOT(2), SLOT(3), 0);                 // Mnh Wh
    gemm1_kernel<<<1, 256>>>(SLOT(3), SLOT(1), SLOT(4), 0);                 // Wc
    jacobi_kernel<<<1, 256>>>(SLOT(4), SLOT(5), SLOT(6), F_SQRT, F_INVSQRT);// Wch, Wcnh
    gemm1_kernel<<<1, 256>>>(SLOT(6), SLOT(2), SLOT(7), 0);                 // P = Wcnh Wh
    gemm1_kernel<<<1, 256>>>(SLOT(0), SLOT(5), SLOT(8), 0);                 // Q = Mh Wch
    gemm1_kernel<<<1, 256>>>(SLOT(8), SLOT(8), SLOT(9), 1);                 // R = Q^T Q

    // Xp = X^{1/2}; Xc = Mnh Xp Mnh
    jacobi_kernel<<<NB, 256>>>(X, bufA, bufA, F_SQRT, F_NONE);
    cong_kernel<<<NB, 256>>>(SLOT(1), bufA, SLOT(1), bufB, 0, 0);           // Xc

    // bary_geom: 1 Karcher step from arithmetic mean
    mean_kernel<<<16, 256>>>(bufB, SLOT(10));                               // G0
    jacobi_kernel<<<1, 256>>>(SLOT(10), SLOT(11), SLOT(12), F_SQRT, F_INVSQRT);
    cong_kernel<<<NB, 256>>>(SLOT(12), bufB, SLOT(12), bufC, 0, 0);
    jacobi_kernel<<<NB, 256>>>(bufC, bufA, bufA, F_LOG, F_NONE);
    mean_kernel<<<16, 256>>>(bufA, SLOT(13));                               // Tm
    jacobi_kernel<<<1, 256>>>(SLOT(13), SLOT(14), SLOT(14), F_EXP, F_NONE);
    gemm1_kernel<<<1, 256>>>(SLOT(11), SLOT(14), SLOT(3), 0);
    gemm1_kernel<<<1, 256>>>(SLOT(3), SLOT(11), SLOT(15), 0);               // G
    jacobi_kernel<<<1, 256>>>(SLOT(15), SLOT(16), SLOT(16), F_INVSQRT, F_NONE); // mnh

    // tangent at I, variance, scale
    cong_kernel<<<NB, 256>>>(SLOT(16), bufB, SLOT(16), bufC, 0, 0);
    jacobi_kernel<<<NB, 256>>>(bufC, bufD, bufD, F_LOG, F_NONE);            // T0
    sumsq_kernel<<<256, 256>>>(bufD);
    finalize_kernel<<<1, 256>>>(shift);

    // arg = factor * P T0 P^T ; E = exp(arg)
    cong_kernel<<<NB, 256>>>(SLOT(7), bufD, SLOT(7), bufC, 1, 1);
    jacobi_kernel<<<NB, 256>>>(bufC, bufA, bufA, F_EXP, F_NONE);            // E

    // out = Q (E R E) Q^T
    gemmB_kernel<<<NB, 256>>>(bufA, SLOT(9), 0, bufC);                      // E R
    gemmB_kernel<<<NB, 256>>>(bufC, bufA, MATSZ, bufD);                     // (E R) E
    cong_kernel<<<NB, 256>>>(SLOT(8), bufD, SLOT(8), out, 0, 1);
    #undef SLOT
}

// round 3
// speedup vs baseline: 1.4756x; 1.4756x over previous
#include <cuda_runtime.h>
#include <math.h>

#define NN 64
#define MATSZ 4096
#define NB 4096
#define PAD 65
#define NSWEEPS 8

enum { F_NONE = -1, F_SQRT = 0, F_INVSQRT = 1, F_LOG = 2, F_EXP = 3 };

// device-global scratch (no runtime allocation allowed)
__device__ float  g_bufA[(size_t)NB * MATSZ];
__device__ float  g_bufB[(size_t)NB * MATSZ];
__device__ float  g_bufC[(size_t)NB * MATSZ];
__device__ float  g_bufD[(size_t)NB * MATSZ];
__device__ float  g_small[20 * MATSZ];
__device__ double g_part[256];
__device__ float  g_scal[4];

__device__ __forceinline__ float apply_fn(int f, float w) {
    switch (f) {
        case F_SQRT:    return sqrtf(fmaxf(w, 0.0f));
        case F_INVSQRT: return rsqrtf(fmaxf(w, 1e-30f));
        case F_LOG:     return logf(fmaxf(w, 1e-30f));
        case F_EXP:     return expf(w);
    }
    return w;
}

// ---------------------------------------------------------------------------
// One-sided (Hestenes) Jacobi eigensolver for symmetric 64x64 matrices.
// Columns stored column-major in shared (PAD=65 -> conflict-free).
// Warp-per-pair rotations; column norms cached in shared and updated
// analytically, so only ONE warp reduction (gamma) per pair.
// For symmetric A: rotated columns a'_j = lambda_j q_j, so
//    V f(L) V^T = sum_j [f(lam_j)/||a'_j||^2] a'_j a'_j^T.
// Indefinite inputs (f=exp on tangents): shift A+cI (c=frob norm), f(lam-c).
// ---------------------------------------------------------------------------
template <int TPB>
__global__ __launch_bounds__(TPB) void jac1s(
    const float* __restrict__ in, float* __restrict__ out1,
    float* __restrict__ out2, int f1, int f2, int useShift)
{
    __shared__ float As[NN * PAD];
    __shared__ float norms[NN];
    __shared__ float gv[NN], gv2[NN];
    __shared__ float red[TPB];
    __shared__ float shift_s;

    const int tid  = threadIdx.x;
    const int lane = tid & 31;
    const int wid  = tid >> 5;
    constexpr int NW = TPB / 32;
    const size_t boff = (size_t)blockIdx.x * MATSZ;

    // load (symmetric input: row-major == col-major); accumulate frob^2
    float fa = 0.0f;
    for (int idx = tid; idx < MATSZ; idx += TPB) {
        int c = idx >> 6, r = idx & 63;
        float v = in[boff + idx];
        As[c * PAD + r] = v;
        fa += v * v;
    }
    red[tid] = fa;
    __syncthreads();
    if (useShift) {                       // uniform branch across block
        #pragma unroll
        for (int s = TPB / 2; s > 0; s >>= 1) {
            if (tid < s) red[tid] += red[tid + s];
            __syncthreads();
        }
        if (tid == 0) shift_s = sqrtf(red[0]) * 1.000001f + 1e-20f;
        __syncthreads();
        if (tid < 64) As[tid * PAD + tid] += shift_s;
    } else {
        if (tid == 0) shift_s = 0.0f;
    }
    __syncthreads();

    // initial column norms
    for (int j = wid; j < 64; j += NW) {
        const float* cp = As + j * PAD;
        float a = cp[lane] * cp[lane] + cp[lane + 32] * cp[lane + 32];
        #pragma unroll
        for (int o = 16; o; o >>= 1) a += __shfl_xor_sync(0xFFFFFFFFu, a, o);
        if (lane == 0) norms[j] = a;
    }
    __syncthreads();

    // sweeps: round-robin tournament, 63 rounds of 32 disjoint pairs
    for (int sw = 0; sw < NSWEEPS; ++sw) {
        for (int r = 0; r < 63; ++r) {
            for (int k = wid; k < 32; k += NW) {
                int p, q;
                if (k == 0) { p = 63; q = r; }
                else        { p = (r + k) % 63; q = (r + 63 - k) % 63; }
                float* cp = As + p * PAD;
                float* cq = As + q * PAD;
                float ap0 = cp[lane], ap1 = cp[lane + 32];
                float aq0 = cq[lane], aq1 = cq[lane + 32];
                float g = ap0 * aq0 + ap1 * aq1;
                #pragma unroll
                for (int o = 16; o; o >>= 1) g += __shfl_xor_sync(0xFFFFFFFFu, g, o);
                if (g != 0.0f) {
                    float al = norms[p], be = norms[q];
                    float tau = (be - al) / (2.0f * g);
                    float t = 1.0f / (fabsf(tau) + sqrtf(1.0f + tau * tau));
                    if (tau < 0.0f) t = -t;
                    float c = rsqrtf(1.0f + t * t);
                    float s = t * c;
                    cp[lane]      = c * ap0 - s * aq0;
                    cp[lane + 32] = c * ap1 - s * aq1;
                    cq[lane]      = s * ap0 + c * aq0;
                    cq[lane + 32] = s * ap1 + c * aq1;
                    if (lane == 0) {
                        float cc = c * c, ss = s * s, cs2 = 2.0f * c * s;
                        norms[p] = cc * al - cs2 * g + ss * be;
                        norms[q] = ss * al + cs2 * g + cc * be;
                    }
                }
            }
            __syncthreads();
        }
    }

    // exact final norms -> eigenvalues -> reconstruction coefficients
    for (int j = wid; j < 64; j += NW) {
        const float* cp = As + j * PAD;
        float a = cp[lane] * cp[lane] + cp[lane + 32] * cp[lane + 32];
        #pragma unroll
        for (int o = 16; o; o >>= 1) a += __shfl_xor_sync(0xFFFFFFFFu, a, o);
        if (lane == 0) {
            a = fmaxf(a, 1e-30f);
            float lam = sqrtf(a) - shift_s;   // shift_s = 0 unless useShift
            gv[j] = apply_fn(f1, lam) / a;
            if (f2 != F_NONE) gv2[j] = apply_fn(f2, lam) / a;
        }
    }
    __syncthreads();

    // out = sum_k gv[k] * col_k col_k^T   (register-tiled)
    constexpr int TR = (TPB >= 1024) ? 2 : 4;
    constexpr int GJ = 64 / TR;
    const int ti = (tid / GJ) * TR;
    const int tj = (tid % GJ) * TR;
    {
        float acc[TR][TR] = {};
        #pragma unroll 4
        for (int k = 0; k < 64; ++k) {
            const float* ck = As + k * PAD;
            float gk = gv[k];
            float a[TR], b[TR];
            #pragma unroll
            for (int r = 0; r < TR; ++r) a[r] = gk * ck[ti + r];
            #pragma unroll
            for (int c = 0; c < TR; ++c) b[c] = ck[tj + c];
            #pragma unroll
            for (int r = 0; r < TR; ++r)
                #pragma unroll
                for (int c = 0; c < TR; ++c) acc[r][c] += a[r] * b[c];
        }
        #pragma unroll
        for (int r = 0; r < TR; ++r)
            #pragma unroll
            for (int c = 0; c < TR; ++c)
                out1[boff + (size_t)(ti + r) * 64 + tj + c] = acc[r][c];
    }
    if (f2 != F_NONE) {
        float acc[TR][TR] = {};
        #pragma unroll 4
        for (int k = 0; k < 64; ++k) {
            const float* ck = As + k * PAD;
            float gk = gv2[k];
            float a[TR], b[TR];
            #pragma unroll
            for (int r = 0; r < TR; ++r) a[r] = gk * ck[ti + r];
            #pragma unroll
            for (int c = 0; c < TR; ++c) b[c] = ck[tj + c];
            #pragma unroll
            for (int r = 0; r < TR; ++r)
                #pragma unroll
                for (int c = 0; c < TR; ++c) acc[r][c] += a[r] * b[c];
        }
        #pragma unroll
        for (int r = 0; r < TR; ++r)
            #pragma unroll
            for (int c = 0; c < TR; ++c)
                out2[boff + (size_t)(ti + r) * 64 + tj + c] = acc[r][c];
    }
}

// 4x4 register tile inner product: C[ti..][tj..] += op(A) op(B)
template <int TA, int TB>
__device__ __forceinline__ void tile_mm(const float* __restrict__ A,
                                        const float* __restrict__ B,
                                        float acc[4][4], int ti, int tj)
{
    #pragma unroll 4
    for (int k = 0; k < 64; ++k) {
        float a[4], b[4];
        #pragma unroll
        for (int r = 0; r < 4; ++r) a[r] = TA ? A[k * 64 + ti + r] : A[(ti + r) * 64 + k];
        #pragma unroll
        for (int c = 0; c < 4; ++c) b[c] = TB ? B[(tj + c) * 64 + k] : B[k * 64 + tj + c];
        #pragma unroll
        for (int r = 0; r < 4; ++r)
            #pragma unroll
            for (int c = 0; c < 4; ++c) acc[r][c] += a[r] * b[c];
    }
}

// out_b = scale * L @ X_b @ op(R)  (L, R broadcast)
__global__ __launch_bounds__(256) void cong_kernel(
    const float* __restrict__ Lm, const float* __restrict__ Xb,
    const float* __restrict__ Rm, float* __restrict__ out,
    int useScale, int transR)
{
    __shared__ float Ls[MATSZ], Rs[MATSZ], Xs[MATSZ];
    const int tid = threadIdx.x;
    const size_t boff = (size_t)blockIdx.x * MATSZ;
    for (int i = tid; i < MATSZ; i += 256) {
        Ls[i] = Lm[i]; Rs[i] = Rm[i]; Xs[i] = Xb[boff + i];
    }
    __syncthreads();

    const int ti = (tid >> 4) << 2, tj = (tid & 15) << 2;
    float acc[4][4] = {};
    tile_mm<0, 0>(Ls, Xs, acc, ti, tj);       // T = L @ X
    __syncthreads();
    #pragma unroll
    for (int r = 0; r < 4; ++r)
        #pragma unroll
        for (int c = 0; c < 4; ++c) Xs[(ti + r) * 64 + tj + c] = acc[r][c];
    __syncthreads();

    float sc = useScale ? g_scal[0] : 1.0f;
    float acc2[4][4] = {};
    if (transR) tile_mm<0, 1>(Xs, Rs, acc2, ti, tj);
    else        tile_mm<0, 0>(Xs, Rs, acc2, ti, tj);
    #pragma unroll
    for (int r = 0; r < 4; ++r) {
        float4 v = make_float4(acc2[r][0] * sc, acc2[r][1] * sc,
                               acc2[r][2] * sc, acc2[r][3] * sc);
        *reinterpret_cast<float4*>(out + boff + (size_t)(ti + r) * 64 + tj) = v;
    }
}

// out_b = A_b @ B_(b*strideB)   (strideB = 0 broadcasts B)
__global__ __launch_bounds__(256) void gemmB_kernel(
    const float* __restrict__ A, const float* __restrict__ Bm, int strideB,
    float* __restrict__ out)
{
    __shared__ float As_[MATSZ], Bs_[MATSZ];
    const int tid = threadIdx.x;
    const size_t boff = (size_t)blockIdx.x * MATSZ;
    const float* Bb = Bm + (size_t)blockIdx.x * strideB;
    for (int i = tid; i < MATSZ; i += 256) { As_[i] = A[boff + i]; Bs_[i] = Bb[i]; }
    __syncthreads();
    const int ti = (tid >> 4) << 2, tj = (tid & 15) << 2;
    float acc[4][4] = {};
    tile_mm<0, 0>(As_, Bs_, acc, ti, tj);
    #pragma unroll
    for (int r = 0; r < 4; ++r) {
        float4 v = make_float4(acc[r][0], acc[r][1], acc[r][2], acc[r][3]);
        *reinterpret_cast<float4*>(out + boff + (size_t)(ti + r) * 64 + tj) = v;
    }
}

// single 64x64 gemm: C = op(A) @ B
__global__ __launch_bounds__(256) void gemm1_kernel(
    const float* __restrict__ A, const float* __restrict__ B,
    float* __restrict__ C, int transA)
{
    __shared__ float As_[MATSZ], Bs_[MATSZ];
    const int tid = threadIdx.x;
    for (int i = tid; i < MATSZ; i += 256) { As_[i] = A[i]; Bs_[i] = B[i]; }
    __syncthreads();
    const int ti = (tid >> 4) << 2, tj = (tid & 15) << 2;
    float acc[4][4] = {};
    if (transA) tile_mm<1, 0>(As_, Bs_, acc, ti, tj);
    else        tile_mm<0, 0>(As_, Bs_, acc, ti, tj);
    #pragma unroll
    for (int r = 0; r < 4; ++r) {
        float4 v = make_float4(acc[r][0], acc[r][1], acc[r][2], acc[r][3]);
        *reinterpret_cast<float4*>(C + (size_t)(ti + r) * 64 + tj) = v;
    }
}

// out[e] = mean_b in[b*4096 + e]
__global__ void mean_kernel(const float* __restrict__ in, float* __restrict__ out)
{
    int e = blockIdx.x * blockDim.x + threadIdx.x;
    double a0 = 0, a1 = 0, a2 = 0, a3 = 0;
    for (int b = 0; b < NB; b += 4) {
        a0 += (double)in[(size_t)(b + 0) * MATSZ + e];
        a1 += (double)in[(size_t)(b + 1) * MATSZ + e];
        a2 += (double)in[(size_t)(b + 2) * MATSZ + e];
        a3 += (double)in[(size_t)(b + 3) * MATSZ + e];
    }
    out[e] = (float)((a0 + a1 + a2 + a3) * (1.0 / (double)NB));
}

// deterministic two-pass sum of squares
__global__ __launch_bounds__(256) void sumsq_kernel(const float* __restrict__ in)
{
    __shared__ double sh[256];
    const int tid = threadIdx.x;
    const size_t base = (size_t)blockIdx.x * 65536;
    double a = 0;
    for (int i = tid; i < 65536; i += 256) {
        float v = in[base + i];
        a += (double)v * (double)v;
    }
    sh[tid] = a;
    __syncthreads();
    for (int s = 128; s > 0; s >>= 1) {
        if (tid < s) sh[tid] += sh[tid + s];
        __syncthreads();
    }
    if (tid == 0) g_part[blockIdx.x] = sh[0];
}

__global__ void finalize_kernel(const float* __restrict__ shift)
{
    __shared__ double sh[256];
    const int tid = threadIdx.x;
    sh[tid] = g_part[tid];
    __syncthreads();
    for (int s = 128; s > 0; s >>= 1) {
        if (tid < s) sh[tid] += sh[tid + s];
        __syncthreads();
    }
    if (tid == 0) {
        double var = sh[0] / (double)NB;
        g_scal[0] = shift[0] / (float)sqrt(var + 1e-5);
    }
}

extern "C" void kernel_launch(void* const* d_in, const int* in_sizes, int n_in,
                              void* d_out, int out_size)
{
    const float* X     = (const float*)d_in[0];
    const float* W     = (const float*)d_in[1];
    const float* M     = (const float*)d_in[2];
    const float* shift = (const float*)d_in[3];
    float* out = (float*)d_out;

    float *bufA, *bufB, *bufC, *bufD, *sm;
    cudaGetSymbolAddress((void**)&bufA, g_bufA);
    cudaGetSymbolAddress((void**)&bufB, g_bufB);
    cudaGetSymbolAddress((void**)&bufC, g_bufC);
    cudaGetSymbolAddress((void**)&bufD, g_bufD);
    cudaGetSymbolAddress((void**)&sm,   g_small);
    #define SLOT(i) (sm + (i) * MATSZ)
    // slots: 0 Mh, 1 Mnh, 2 Wh, 3 tmp, 4 Wc, 5 Wch, 6 Wcnh, 7 P, 8 Q, 9 R,
    //        10 G0, 11 G0h, 12 G0nh, 13 Tm, 14 expTm, 15 G, 16 mnh

    // parameter prep (tiny single-matrix ops; 1024 threads = 1 pair/warp)
    jac1s<1024><<<1, 1024>>>(M, SLOT(0), SLOT(1), F_SQRT, F_INVSQRT, 0);     // Mh, Mnh
    jac1s<1024><<<1, 1024>>>(W, SLOT(2), SLOT(2), F_SQRT, F_NONE, 0);        // Wh
    gemm1_kernel<<<1, 256>>>(SLOT(1), SLOT(2), SLOT(3), 0);                  // Mnh Wh
    gemm1_kernel<<<1, 256>>>(SLOT(3), SLOT(1), SLOT(4), 0);                  // Wc
    jac1s<1024><<<1, 1024>>>(SLOT(4), SLOT(5), SLOT(6), F_SQRT, F_INVSQRT, 0); // Wch, Wcnh
    gemm1_kernel<<<1, 256>>>(SLOT(6), SLOT(2), SLOT(7), 0);                  // P = Wcnh Wh
    gemm1_kernel<<<1, 256>>>(SLOT(0), SLOT(5), SLOT(8), 0);                  // Q = Mh Wch
    gemm1_kernel<<<1, 256>>>(SLOT(8), SLOT(8), SLOT(9), 1);                  // R = Q^T Q

    // Xp = X^{1/2}; Xc = Mnh Xp Mnh
    jac1s<256><<<NB, 256>>>(X, bufA, bufA, F_SQRT, F_NONE, 0);
    cong_kernel<<<NB, 256>>>(SLOT(1), bufA, SLOT(1), bufB, 0, 0);            // Xc

    // bary_geom: 1 Karcher step from arithmetic mean
    mean_kernel<<<16, 256>>>(bufB, SLOT(10));                                // G0
    jac1s<1024><<<1, 1024>>>(SLOT(10), SLOT(11), SLOT(12), F_SQRT, F_INVSQRT, 0);
    cong_kernel<<<NB, 256>>>(SLOT(12), bufB, SLOT(12), bufC, 0, 0);
    jac1s<256><<<NB, 256>>>(bufC, bufA, bufA, F_LOG, F_NONE, 0);
    mean_kernel<<<16, 256>>>(bufA, SLOT(13));                                // Tm
    jac1s<1024><<<1, 1024>>>(SLOT(13), SLOT(14), SLOT(14), F_EXP, F_NONE, 1); // exp (indefinite -> shift)
    gemm1_kernel<<<1, 256>>>(SLOT(11), SLOT(14), SLOT(3), 0);
    gemm1_kernel<<<1, 256>>>(SLOT(3), SLOT(11), SLOT(15), 0);                // G
    jac1s<1024><<<1, 1024>>>(SLOT(15), SLOT(16), SLOT(16), F_INVSQRT, F_NONE, 0); // mnh

    // tangent at I, variance, scale
    cong_kernel<<<NB, 256>>>(SLOT(16), bufB, SLOT(16), bufC, 0, 0);
    jac1s<256><<<NB, 256>>>(bufC, bufD, bufD, F_LOG, F_NONE, 0);             // T0
    sumsq_kernel<<<256, 256>>>(bufD);
    finalize_kernel<<<1, 256>>>(shift);

    // arg = factor * P T0 P^T ; E = exp(arg)  (indefinite -> shift)
    cong_kernel<<<NB, 256>>>(SLOT(7), bufD, SLOT(7), bufC, 1, 1);
    jac1s<256><<<NB, 256>>>(bufC, bufA, bufA, F_EXP, F_NONE, 1);             // E

    // out = Q (E R E) Q^T
    gemmB_kernel<<<NB, 256>>>(bufA, SLOT(9), 0, bufC);                       // E R
    gemmB_kernel<<<NB, 256>>>(bufC, bufA, MATSZ, bufD);                      // (E R) E
    cong_kernel<<<NB, 256>>>(SLOT(8), bufD, SLOT(8), out, 0, 1);
    #undef SLOT
}

// round 5
// speedup vs baseline: 1.8429x; 1.2489x over previous
#include <cuda_runtime.h>
#include <math.h>

#define NN 64
#define MATSZ 4096
#define NB 4096

enum { F_NONE = -1, F_SQRT = 0, F_INVSQRT = 1, F_LOG = 2, F_EXP = 3 };

// device-global scratch (no runtime allocation allowed)
__device__ float  g_bufA[(size_t)NB * MATSZ];
__device__ float  g_bufB[(size_t)NB * MATSZ];
__device__ float  g_bufC[(size_t)NB * MATSZ];
__device__ float  g_bufD[(size_t)NB * MATSZ];
__device__ float  g_small[20 * MATSZ];
__device__ double g_part[256];
__device__ float  g_scal[4];

__device__ __forceinline__ float apply_fn(int f, float w) {
    switch (f) {
        case F_SQRT:    return sqrtf(fmaxf(w, 0.0f));
        case F_INVSQRT: return rsqrtf(fmaxf(w, 1e-30f));
        case F_LOG:     return logf(fmaxf(w, 1e-30f));
        case F_EXP:     return expf(w);
    }
    return w;
}

// ---------------------------------------------------------------------------
// One-sided (Hestenes) Jacobi eigensolver, symmetric 64x64.
// Columns in shared as float2 (32 float2/column, pad 33 -> conflict-free).
// Warp-per-pair rotations with PPW independent pairs interleaved in registers
// so their shuffle-reduction chains overlap. Column norms cached in shared,
// updated analytically (one warp reduction per pair).
// Symmetric A: rotated columns a'_j = lambda_j q_j, so
//    V f(L) V^T = sum_j [f(lam_j)/||a'_j||^2] a'_j a'_j^T.
// Indefinite input (f=exp on tangents): diagonalize A + c*I (c = ||A||_F),
// apply f(lam - c). Final norms recomputed exactly.
// ---------------------------------------------------------------------------
template <int TPB>
__global__ __launch_bounds__(TPB) void jac1s(
    const float* __restrict__ in, float* __restrict__ out1,
    float* __restrict__ out2, int f1, int f2, int useShift, int nsweeps)
{
    constexpr int NW  = TPB / 32;   // warps per block
    constexpr int PPW = 32 / NW;    // pairs per warp (512 -> 2, 1024 -> 1)
    __shared__ float2 As2[NN * 33];
    __shared__ float norms[NN];
    __shared__ float gv[NN], gv2[NN];
    __shared__ float red[TPB];
    __shared__ float shift_s;
    float* Asf = reinterpret_cast<float*>(As2);

    const int tid  = threadIdx.x;
    const int lane = tid & 31;
    const int wid  = tid >> 5;
    const size_t boff = (size_t)blockIdx.x * MATSZ;

    // load (symmetric: row c of input == column c); accumulate frob^2
    float fa = 0.0f;
    for (int idx = tid; idx < MATSZ; idx += TPB) {
        int c = idx >> 6, r = idx & 63;
        float v = in[boff + idx];
        Asf[c * 66 + r] = v;
        fa += v * v;
    }
    red[tid] = fa;
    __syncthreads();
    if (useShift) {
        #pragma unroll
        for (int s = TPB / 2; s > 0; s >>= 1) {
            if (tid < s) red[tid] += red[tid + s];
            __syncthreads();
        }
        if (tid == 0) shift_s = sqrtf(red[0]) * 1.000001f + 1e-20f;
        __syncthreads();
        if (tid < 64) Asf[tid * 66 + tid] += shift_s;
    } else {
        if (tid == 0) shift_s = 0.0f;
    }
    __syncthreads();

    // initial column norms
    for (int j = wid; j < 64; j += NW) {
        float2 a = As2[j * 33 + lane];
        float s = a.x * a.x + a.y * a.y;
        #pragma unroll
        for (int o = 16; o; o >>= 1) s += __shfl_xor_sync(0xFFFFFFFFu, s, o);
        if (lane == 0) norms[j] = s;
    }
    __syncthreads();

    // sweeps: round-robin tournament, 63 rounds x 32 disjoint pairs
    for (int sw = 0; sw < nsweeps; ++sw) {
        for (int r = 0; r < 63; ++r) {
            int   p[PPW], q[PPW];
            float2 ap[PPW], aq[PPW];
            float g[PPW];
            #pragma unroll
            for (int u = 0; u < PPW; ++u) {
                int k = wid + u * NW;
                if (k == 0) { p[u] = 63; q[u] = r; }
                else {
                    int a1 = r + k;      p[u] = (a1 < 63) ? a1 : a1 - 63;
                    int a2 = r + 63 - k; q[u] = (a2 < 63) ? a2 : a2 - 63;
                }
                ap[u] = As2[p[u] * 33 + lane];
                aq[u] = As2[q[u] * 33 + lane];
                g[u] = ap[u].x * aq[u].x + ap[u].y * aq[u].y;
            }
            #pragma unroll
            for (int o = 16; o; o >>= 1) {
                #pragma unroll
                for (int u = 0; u < PPW; ++u)
                    g[u] += __shfl_xor_sync(0xFFFFFFFFu, g[u], o);
            }
            #pragma unroll
            for (int u = 0; u < PPW; ++u) {
                if (g[u] != 0.0f) {
                    float al = norms[p[u]], be = norms[q[u]];
                    float tau = (be - al) / (2.0f * g[u]);
                    float t = 1.0f / (fabsf(tau) + sqrtf(1.0f + tau * tau));
                    if (tau < 0.0f) t = -t;
                    float c = rsqrtf(1.0f + t * t);
                    float s = t * c;
                    float2 np, nq;
                    np.x = c * ap[u].x - s * aq[u].x;
                    np.y = c * ap[u].y - s * aq[u].y;
                    nq.x = s * ap[u].x + c * aq[u].x;
                    nq.y = s * ap[u].y + c * aq[u].y;
                    As2[p[u] * 33 + lane] = np;
                    As2[q[u] * 33 + lane] = nq;
                    if (lane == 0) {
                        float cc = c * c, ss = s * s, cs2 = 2.0f * c * s;
                        norms[p[u]] = cc * al - cs2 * g[u] + ss * be;
                        norms[q[u]] = ss * al + cs2 * g[u] + cc * be;
                    }
                }
            }
            __syncthreads();
        }
    }

    // exact final norms -> eigenvalues -> reconstruction coefficients
    for (int j = wid; j < 64; j += NW) {
        float2 a = As2[j * 33 + lane];
        float s = a.x * a.x + a.y * a.y;
        #pragma unroll
        for (int o = 16; o; o >>= 1) s += __shfl_xor_sync(0xFFFFFFFFu, s, o);
        if (lane == 0) {
            s = fmaxf(s, 1e-30f);
            float lam = sqrtf(s) - shift_s;
            gv[j] = apply_fn(f1, lam) / s;
            if (f2 != F_NONE) gv2[j] = apply_fn(f2, lam) / s;
        }
    }
    __syncthreads();

    // out = sum_k gv[k] * col_k col_k^T  (TRI x 4 register tiles)
    constexpr int TRI = MATSZ / TPB / 4;   // 512 -> 2, 1024 -> 1
    const int ti = (tid >> 4) * TRI;
    const int tj = (tid & 15) << 2;
    {
        float acc[TRI][4] = {};
        #pragma unroll 4
        for (int k = 0; k < 64; ++k) {
            const float* ck = Asf + k * 66;
            float gk = gv[k];
            float a[TRI], b[4];
            #pragma unroll
            for (int r = 0; r < TRI; ++r) a[r] = gk * ck[ti + r];
            #pragma unroll
            for (int c = 0; c < 4; ++c) b[c] = ck[tj + c];
            #pragma unroll
            for (int r = 0; r < TRI; ++r)
                #pragma unroll
                for (int c = 0; c < 4; ++c) acc[r][c] += a[r] * b[c];
        }
        #pragma unroll
        for (int r = 0; r < TRI; ++r) {
            float4 v = make_float4(acc[r][0], acc[r][1], acc[r][2], acc[r][3]);
            *reinterpret_cast<float4*>(out1 + boff + (size_t)(ti + r) * 64 + tj) = v;
        }
    }
    if (f2 != F_NONE) {
        float acc[TRI][4] = {};
        #pragma unroll 4
        for (int k = 0; k < 64; ++k) {
            const float* ck = Asf + k * 66;
            float gk = gv2[k];
            float a[TRI], b[4];
            #pragma unroll
            for (int r = 0; r < TRI; ++r) a[r] = gk * ck[ti + r];
            #pragma unroll
            for (int c = 0; c < 4; ++c) b[c] = ck[tj + c];
            #pragma unroll
            for (int r = 0; r < TRI; ++r)
                #pragma unroll
                for (int c = 0; c < 4; ++c) acc[r][c] += a[r] * b[c];
        }
        #pragma unroll
        for (int r = 0; r < TRI; ++r) {
            float4 v = make_float4(acc[r][0], acc[r][1], acc[r][2], acc[r][3]);
            *reinterpret_cast<float4*>(out2 + boff + (size_t)(ti + r) * 64 + tj) = v;
        }
    }
}

// 4x4 register tile inner product: C[ti..][tj..] += op(A) op(B)
template <int TA, int TB>
__device__ __forceinline__ void tile_mm(const float* __restrict__ A,
                                        const float* __restrict__ B,
                                        float acc[4][4], int ti, int tj)
{
    #pragma unroll 4
    for (int k = 0; k < 64; ++k) {
        float a[4], b[4];
        #pragma unroll
        for (int r = 0; r < 4; ++r) a[r] = TA ? A[k * 64 + ti + r] : A[(ti + r) * 64 + k];
        #pragma unroll
        for (int c = 0; c < 4; ++c) b[c] = TB ? B[(tj + c) * 64 + k] : B[k * 64 + tj + c];
        #pragma unroll
        for (int r = 0; r < 4; ++r)
            #pragma unroll
            for (int c = 0; c < 4; ++c) acc[r][c] += a[r] * b[c];
    }
}

// out_b = scale * L @ X_b @ op(R)  (L, R broadcast)
__global__ __launch_bounds__(256) void cong_kernel(
    const float* __restrict__ Lm, const float* __restrict__ Xb,
    const float* __restrict__ Rm, float* __restrict__ out,
    int useScale, int transR)
{
    __shared__ float Ls[MATSZ], Rs[MATSZ], Xs[MATSZ];
    const int tid = threadIdx.x;
    const size_t boff = (size_t)blockIdx.x * MATSZ;
    for (int i = tid; i < MATSZ; i += 256) {
        Ls[i] = Lm[i]; Rs[i] = Rm[i]; Xs[i] = Xb[boff + i];
    }
    __syncthreads();

    const int ti = (tid >> 4) << 2, tj = (tid & 15) << 2;
    float acc[4][4] = {};
    tile_mm<0, 0>(Ls, Xs, acc, ti, tj);       // T = L @ X
    __syncthreads();
    #pragma unroll
    for (int r = 0; r < 4; ++r)
        #pragma unroll
        for (int c = 0; c < 4; ++c) Xs[(ti + r) * 64 + tj + c] = acc[r][c];
    __syncthreads();

    float sc = useScale ? g_scal[0] : 1.0f;
    float acc2[4][4] = {};
    if (transR) tile_mm<0, 1>(Xs, Rs, acc2, ti, tj);
    else        tile_mm<0, 0>(Xs, Rs, acc2, ti, tj);
    #pragma unroll
    for (int r = 0; r < 4; ++r) {
        float4 v = make_float4(acc2[r][0] * sc, acc2[r][1] * sc,
                               acc2[r][2] * sc, acc2[r][3] * sc);
        *reinterpret_cast<float4*>(out + boff + (size_t)(ti + r) * 64 + tj) = v;
    }
}

// out_b = A_b @ B_(b*strideB)   (strideB = 0 broadcasts B)
__global__ __launch_bounds__(256) void gemmB_kernel(
    const float* __restrict__ A, const float* __restrict__ Bm, int strideB,
    float* __restrict__ out)
{
    __shared__ float As_[MATSZ], Bs_[MATSZ];
    const int tid = threadIdx.x;
    const size_t boff = (size_t)blockIdx.x * MATSZ;
    const float* Bb = Bm + (size_t)blockIdx.x * strideB;
    for (int i = tid; i < MATSZ; i += 256) { As_[i] = A[boff + i]; Bs_[i] = Bb[i]; }
    __syncthreads();
    const int ti = (tid >> 4) << 2, tj = (tid & 15) << 2;
    float acc[4][4] = {};
    tile_mm<0, 0>(As_, Bs_, acc, ti, tj);
    #pragma unroll
    for (int r = 0; r < 4; ++r) {
        float4 v = make_float4(acc[r][0], acc[r][1], acc[r][2], acc[r][3]);
        *reinterpret_cast<float4*>(out + boff + (size_t)(ti + r) * 64 + tj) = v;
    }
}

// single 64x64 gemm: C = op(A) @ B
__global__ __launch_bounds__(256) void gemm1_kernel(
    const float* __restrict__ A, const float* __restrict__ B,
    float* __restrict__ C, int transA)
{
    __shared__ float As_[MATSZ], Bs_[MATSZ];
    const int tid = threadIdx.x;
    for (int i = tid; i < MATSZ; i += 256) { As_[i] = A[i]; Bs_[i] = B[i]; }
    __syncthreads();
    const int ti = (tid >> 4) << 2, tj = (tid & 15) << 2;
    float acc[4][4] = {};
    if (transA) tile_mm<1, 0>(As_, Bs_, acc, ti, tj);
    else        tile_mm<0, 0>(As_, Bs_, acc, ti, tj);
    #pragma unroll
    for (int r = 0; r < 4; ++r) {
        float4 v = make_float4(acc[r][0], acc[r][1], acc[r][2], acc[r][3]);
        *reinterpret_cast<float4*>(C + (size_t)(ti + r) * 64 + tj) = v;
    }
}

// out[e] = mean_b in[b*4096 + e]
__global__ void mean_kernel(const float* __restrict__ in, float* __restrict__ out)
{
    int e = blockIdx.x * blockDim.x + threadIdx.x;
    double a0 = 0, a1 = 0, a2 = 0, a3 = 0;
    for (int b = 0; b < NB; b += 4) {
        a0 += (double)in[(size_t)(b + 0) * MATSZ + e];
        a1 += (double)in[(size_t)(b + 1) * MATSZ + e];
        a2 += (double)in[(size_t)(b + 2) * MATSZ + e];
        a3 += (double)in[(size_t)(b + 3) * MATSZ + e];
    }
    out[e] = (float)((a0 + a1 + a2 + a3) * (1.0 / (double)NB));
}

// deterministic two-pass sum of squares
__global__ __launch_bounds__(256) void sumsq_kernel(const float* __restrict__ in)
{
    __shared__ double sh[256];
    const int tid = threadIdx.x;
    const size_t base = (size_t)blockIdx.x * 65536;
    double a = 0;
    for (int i = tid; i < 65536; i += 256) {
        float v = in[base + i];
        a += (double)v * (double)v;
    }
    sh[tid] = a;
    __syncthreads();
    for (int s = 128; s > 0; s >>= 1) {
        if (tid < s) sh[tid] += sh[tid + s];
        __syncthreads();
    }
    if (tid == 0) g_part[blockIdx.x] = sh[0];
}

__global__ void finalize_kernel(const float* __restrict__ shift)
{
    __shared__ double sh[256];
    const int tid = threadIdx.x;
    sh[tid] = g_part[tid];
    __syncthreads();
    for (int s = 128; s > 0; s >>= 1) {
        if (tid < s) sh[tid] += sh[tid + s];
        __syncthreads();
    }
    if (tid == 0) {
        double var = sh[0] / (double)NB;
        g_scal[0] = shift[0] / (float)sqrt(var + 1e-5);
    }
}

extern "C" void kernel_launch(void* const* d_in, const int* in_sizes, int n_in,
                              void* d_out, int out_size)
{
    const float* X     = (const float*)d_in[0];
    const float* W     = (const float*)d_in[1];
    const float* M     = (const float*)d_in[2];
    const float* shift = (const float*)d_in[3];
    float* out = (float*)d_out;

    float *bufA, *bufB, *bufC, *bufD, *sm;
    cudaGetSymbolAddress((void**)&bufA, g_bufA);
    cudaGetSymbolAddress((void**)&bufB, g_bufB);
    cudaGetSymbolAddress((void**)&bufC, g_bufC);
    cudaGetSymbolAddress((void**)&bufD, g_bufD);
    cudaGetSymbolAddress((void**)&sm,   g_small);
    #define SLOT(i) (sm + (i) * MATSZ)
    // slots: 0 Mh, 1 Mnh, 2 Wh, 3 tmp, 4 Wc, 5 Wch, 6 Wcnh, 7 P, 8 Q, 9 R,
    //        10 G0, 11 G0h, 12 G0nh, 13 Tm, 14 expTm, 15 G, 16 mnh

    // parameter prep (tiny single-matrix ops; full 8 sweeps, cost negligible)
    jac1s<1024><<<1, 1024>>>(M, SLOT(0), SLOT(1), F_SQRT, F_INVSQRT, 0, 8);   // Mh, Mnh
    jac1s<1024><<<1, 1024>>>(W, SLOT(2), SLOT(2), F_SQRT, F_NONE, 0, 8);      // Wh
    gemm1_kernel<<<1, 256>>>(SLOT(1), SLOT(2), SLOT(3), 0);                   // Mnh Wh
    gemm1_kernel<<<1, 256>>>(SLOT(3), SLOT(1), SLOT(4), 0);                   // Wc
    jac1s<1024><<<1, 1024>>>(SLOT(4), SLOT(5), SLOT(6), F_SQRT, F_INVSQRT, 0, 8); // Wch, Wcnh
    gemm1_kernel<<<1, 256>>>(SLOT(6), SLOT(2), SLOT(7), 0);                   // P = Wcnh Wh
    gemm1_kernel<<<1, 256>>>(SLOT(0), SLOT(5), SLOT(8), 0);                   // Q = Mh Wch
    gemm1_kernel<<<1, 256>>>(SLOT(8), SLOT(8), SLOT(9), 1);                   // R = Q^T Q

    // Xp = X^{1/2}; Xc = Mnh Xp Mnh
    jac1s<512><<<NB, 512>>>(X, bufA, bufA, F_SQRT, F_NONE, 0, 7);
    cong_kernel<<<NB, 256>>>(SLOT(1), bufA, SLOT(1), bufB, 0, 0);             // Xc

    // bary_geom: 1 Karcher step from arithmetic mean
    mean_kernel<<<16, 256>>>(bufB, SLOT(10));                                 // G0
    jac1s<1024><<<1, 1024>>>(SLOT(10), SLOT(11), SLOT(12), F_SQRT, F_INVSQRT, 0, 8);
    cong_kernel<<<NB, 256>>>(SLOT(12), bufB, SLOT(12), bufC, 0, 0);
    jac1s<512><<<NB, 512>>>(bufC, bufA, bufA, F_LOG, F_NONE, 0, 7);
    mean_kernel<<<16, 256>>>(bufA, SLOT(13));                                 // Tm
    jac1s<1024><<<1, 1024>>>(SLOT(13), SLOT(14), SLOT(14), F_EXP, F_NONE, 1, 8); // exp (shift)
    gemm1_kernel<<<1, 256>>>(SLOT(11), SLOT(14), SLOT(3), 0);
    gemm1_kernel<<<1, 256>>>(SLOT(3), SLOT(11), SLOT(15), 0);                 // G
    jac1s<1024><<<1, 1024>>>(SLOT(15), SLOT(16), SLOT(16), F_INVSQRT, F_NONE, 0, 8); // mnh

    // tangent at I, variance, scale
    cong_kernel<<<NB, 256>>>(SLOT(16), bufB, SLOT(16), bufC, 0, 0);
    jac1s<512><<<NB, 512>>>(bufC, bufD, bufD, F_LOG, F_NONE, 0, 7);           // T0
    sumsq_kernel<<<256, 256>>>(bufD);
    finalize_kernel<<<1, 256>>>(shift);

    // arg = factor * P T0 P^T ; E = exp(arg)  (indefinite -> shift)
    cong_kernel<<<NB, 256>>>(SLOT(7), bufD, SLOT(7), bufC, 1, 1);
    jac1s<512><<<NB, 512>>>(bufC, bufA, bufA, F_EXP, F_NONE, 1, 7);           // E

    // out = Q (E R E) Q^T
    gemmB_kernel<<<NB, 256>>>(bufA, SLOT(9), 0, bufC);                        // E R
    gemmB_kernel<<<NB, 256>>>(bufC, bufA, MATSZ, bufD);                       // (E R) E
    cong_kernel<<<NB, 256>>>(SLOT(8), bufD, SLOT(8), out, 0, 1);
    #undef SLOT
}

// round 6
// speedup vs baseline: 2.8171x; 1.5286x over previous
#include <cuda_runtime.h>
#include <math.h>

#define NN 64
#define MATSZ 4096
#define NB 4096

enum { F_NONE = -1, F_SQRT = 0, F_INVSQRT = 1, F_LOG = 2, F_EXP = 3 };

// device-global scratch (no runtime allocation allowed)
__device__ float  g_bufA[(size_t)NB * MATSZ];
__device__ float  g_bufB[(size_t)NB * MATSZ];
__device__ float  g_bufC[(size_t)NB * MATSZ];
__device__ float  g_bufD[(size_t)NB * MATSZ];
__device__ float  g_small[20 * MATSZ];
__device__ double g_part[256];
__device__ float  g_scal[4];

__device__ __forceinline__ float apply_fn(int f, float w) {
    switch (f) {
        case F_SQRT:    return sqrtf(fmaxf(w, 0.0f));
        case F_INVSQRT: return rsqrtf(fmaxf(w, 1e-30f));
        case F_LOG:     return logf(fmaxf(w, 1e-30f));
        case F_EXP:     return expf(w);
    }
    return w;
}

// ---------------------------------------------------------------------------
// In-shared 64x64 GEMM helper: C = alpha*(A@B) + beta*D + diag*I.
// 256 threads, 4x4 tiles. C must differ from A and B. D==C or D==A allowed
// (D is read per-own-tile after the internal barrier). Trailing barrier
// makes C immediately consumable.
// ---------------------------------------------------------------------------
__device__ __forceinline__ void mm64(const float* __restrict__ A,
                                     const float* __restrict__ B,
                                     float alpha, float beta,
                                     const float* __restrict__ D,
                                     float diag, float* __restrict__ C, int tid)
{
    const int ti = (tid >> 4) << 2, tj = (tid & 15) << 2;
    float acc[4][4] = {};
    #pragma unroll 4
    for (int k = 0; k < 64; ++k) {
        float a0 = A[(ti + 0) * 64 + k], a1 = A[(ti + 1) * 64 + k];
        float a2 = A[(ti + 2) * 64 + k], a3 = A[(ti + 3) * 64 + k];
        float4 b = *reinterpret_cast<const float4*>(B + k * 64 + tj);
        acc[0][0] += a0 * b.x; acc[0][1] += a0 * b.y; acc[0][2] += a0 * b.z; acc[0][3] += a0 * b.w;
        acc[1][0] += a1 * b.x; acc[1][1] += a1 * b.y; acc[1][2] += a1 * b.z; acc[1][3] += a1 * b.w;
        acc[2][0] += a2 * b.x; acc[2][1] += a2 * b.y; acc[2][2] += a2 * b.z; acc[2][3] += a2 * b.w;
        acc[3][0] += a3 * b.x; acc[3][1] += a3 * b.y; acc[3][2] += a3 * b.z; acc[3][3] += a3 * b.w;
    }
    __syncthreads();   // all reads of A, B complete
    #pragma unroll
    for (int r = 0; r < 4; ++r) {
        float4 v;
        v.x = alpha * acc[r][0]; v.y = alpha * acc[r][1];
        v.z = alpha * acc[r][2]; v.w = alpha * acc[r][3];
        if (beta != 0.0f) {
            float4 d = *reinterpret_cast<const float4*>(D + (ti + r) * 64 + tj);
            v.x += beta * d.x; v.y += beta * d.y; v.z += beta * d.z; v.w += beta * d.w;
        }
        if (diag != 0.0f) {
            int row = ti + r;
            if (row >= tj && row < tj + 4) (&v.x)[row - tj] += diag;
        }
        *reinterpret_cast<float4*>(C + (ti + r) * 64 + tj) = v;
    }
    __syncthreads();
}

// ---------------------------------------------------------------------------
// Batched matrix sqrt via coupled Newton-Schulz (Higham). One CTA/matrix.
// Y0 = X/s (s = ||X||_F / 1.8 so spectrum in (0, 1.8]), Z0 = I.
//   W = Z@Y;  Y' = 1.5Y - 0.5 Y@W;  Z' = 1.5Z - 0.5 W@Z.
// 10 iterations (worst-case spectrum fully converged). out = sqrt(s) * Y.
// ---------------------------------------------------------------------------
__global__ __launch_bounds__(256) void nssqrt_kernel(
    const float* __restrict__ in, float* __restrict__ out)
{
    extern __shared__ float sh[];          // 4 * 4096 floats
    float *Y = sh, *Z = sh + 4096, *W = sh + 8192, *T = sh + 12288;
    __shared__ float red[256];
    __shared__ float s_s;

    const int tid = threadIdx.x;
    const size_t boff = (size_t)blockIdx.x * MATSZ;

    float fa = 0.0f;
    for (int idx = tid; idx < MATSZ; idx += 256) {
        float v = in[boff + idx];
        Y[idx] = v;
        fa += v * v;
        Z[idx] = ((idx >> 6) == (idx & 63)) ? 1.0f : 0.0f;
    }
    red[tid] = fa;
    __syncthreads();
    #pragma unroll
    for (int s = 128; s > 0; s >>= 1) {
        if (tid < s) red[tid] += red[tid + s];
        __syncthreads();
    }
    if (tid == 0) s_s = fmaxf(sqrtf(red[0]) / 1.8f, 1e-20f);
    __syncthreads();
    float inv_s = 1.0f / s_s;
    for (int idx = tid; idx < MATSZ; idx += 256) Y[idx] *= inv_s;
    __syncthreads();

    for (int it = 0; it < 10; ++it) {
        mm64(Z, Y, 1.0f, 0.0f, nullptr, 0.0f, W, tid);      // W = Z@Y
        mm64(Y, W, -0.5f, 1.5f, Y, 0.0f, T, tid);           // T = 1.5Y - 0.5 Y@W
        if (it < 9) {
            mm64(W, Z, -0.5f, 1.5f, Z, 0.0f, Y, tid);       // Znew -> old Y buffer
            float* nY = T; float* nZ = Y; float* nT = Z;
            Y = nY; Z = nZ; T = nT;
        } else {
            Y = T;
        }
    }
    float rs = sqrtf(s_s);
    for (int idx = tid; idx < MATSZ; idx += 256)
        out[boff + idx] = Y[idx] * rs;
}

// ---------------------------------------------------------------------------
// Batched matrix exp via scaling-and-squaring + degree-7 Taylor (Horner).
// One CTA/matrix. j halvings until ||B||_F <= 0.25 (deterministic), then
// E = taylor7(B/2^j) squared j times.
// ---------------------------------------------------------------------------
__global__ __launch_bounds__(256) void expm_kernel(
    const float* __restrict__ in, float* __restrict__ out)
{
    extern __shared__ float sh[];          // 3 * 4096 floats
    float *B = sh, *P = sh + 4096, *Q = sh + 8192;
    __shared__ float red[256];
    __shared__ float sc_s;
    __shared__ int   j_s;

    const int tid = threadIdx.x;
    const size_t boff = (size_t)blockIdx.x * MATSZ;

    float fa = 0.0f;
    for (int idx = tid; idx < MATSZ; idx += 256) {
        float v = in[boff + idx];
        B[idx] = v;
        fa += v * v;
    }
    red[tid] = fa;
    __syncthreads();
    #pragma unroll
    for (int s = 128; s > 0; s >>= 1) {
        if (tid < s) red[tid] += red[tid + s];
        __syncthreads();
    }
    if (tid == 0) {
        float F = sqrtf(red[0]);
        int j = 0;
        while (F > 0.25f && j < 40) { F *= 0.5f; ++j; }
        j_s = j;
        sc_s = exp2f((float)(-j));
    }
    __syncthreads();
    const int j = j_s;
    float sc = sc_s;
    for (int idx = tid; idx < MATSZ; idx += 256) B[idx] *= sc;
    __syncthreads();

    // Horner init: P = c7*B + c6*I
    const float c7 = 1.0f / 5040.0f, c6 = 1.0f / 720.0f;
    for (int idx = tid; idx < MATSZ; idx += 256) {
        float v = c7 * B[idx];
        if ((idx >> 6) == (idx & 63)) v += c6;
        P[idx] = v;
    }
    __syncthreads();
    const float cs[6] = { 1.0f / 120.0f, 1.0f / 24.0f, 1.0f / 6.0f, 0.5f, 1.0f, 1.0f };
    float *cur = P, *oth = Q;
    #pragma unroll
    for (int k = 0; k < 6; ++k) {
        mm64(cur, B, 1.0f, 0.0f, nullptr, cs[k], oth, tid);
        float* t = cur; cur = oth; oth = t;
    }
    for (int t = 0; t < j; ++t) {
        mm64(cur, cur, 1.0f, 0.0f, nullptr, 0.0f, oth, tid);
        float* tt = cur; cur = oth; oth = tt;
    }
    for (int idx = tid; idx < MATSZ; idx += 256)
        out[boff + idx] = cur[idx];
}

// ---------------------------------------------------------------------------
// One-sided (Hestenes) Jacobi eigensolver, symmetric 64x64 (see round 3/5).
// ---------------------------------------------------------------------------
template <int TPB>
__global__ __launch_bounds__(TPB) void jac1s(
    const float* __restrict__ in, float* __restrict__ out1,
    float* __restrict__ out2, int f1, int f2, int useShift, int nsweeps)
{
    constexpr int NW  = TPB / 32;
    constexpr int PPW = 32 / NW;
    __shared__ float2 As2[NN * 33];
    __shared__ float norms[NN];
    __shared__ float gv[NN], gv2[NN];
    __shared__ float red[TPB];
    __shared__ float shift_s;
    float* Asf = reinterpret_cast<float*>(As2);

    const int tid  = threadIdx.x;
    const int lane = tid & 31;
    const int wid  = tid >> 5;
    const size_t boff = (size_t)blockIdx.x * MATSZ;

    float fa = 0.0f;
    for (int idx = tid; idx < MATSZ; idx += TPB) {
        int c = idx >> 6, r = idx & 63;
        float v = in[boff + idx];
        Asf[c * 66 + r] = v;
        fa += v * v;
    }
    red[tid] = fa;
    __syncthreads();
    if (useShift) {
        #pragma unroll
        for (int s = TPB / 2; s > 0; s >>= 1) {
            if (tid < s) red[tid] += red[tid + s];
            __syncthreads();
        }
        if (tid == 0) shift_s = sqrtf(red[0]) * 1.000001f + 1e-20f;
        __syncthreads();
        if (tid < 64) Asf[tid * 66 + tid] += shift_s;
    } else {
        if (tid == 0) shift_s = 0.0f;
    }
    __syncthreads();

    for (int j = wid; j < 64; j += NW) {
        float2 a = As2[j * 33 + lane];
        float s = a.x * a.x + a.y * a.y;
        #pragma unroll
        for (int o = 16; o; o >>= 1) s += __shfl_xor_sync(0xFFFFFFFFu, s, o);
        if (lane == 0) norms[j] = s;
    }
    __syncthreads();

    for (int sw = 0; sw < nsweeps; ++sw) {
        for (int r = 0; r < 63; ++r) {
            int   p[PPW], q[PPW];
            float2 ap[PPW], aq[PPW];
            float g[PPW];
            #pragma unroll
            for (int u = 0; u < PPW; ++u) {
                int k = wid + u * NW;
                if (k == 0) { p[u] = 63; q[u] = r; }
                else {
                    int a1 = r + k;      p[u] = (a1 < 63) ? a1 : a1 - 63;
                    int a2 = r + 63 - k; q[u] = (a2 < 63) ? a2 : a2 - 63;
                }
                ap[u] = As2[p[u] * 33 + lane];
                aq[u] = As2[q[u] * 33 + lane];
                g[u] = ap[u].x * aq[u].x + ap[u].y * aq[u].y;
            }
            #pragma unroll
            for (int o = 16; o; o >>= 1) {
                #pragma unroll
                for (int u = 0; u < PPW; ++u)
                    g[u] += __shfl_xor_sync(0xFFFFFFFFu, g[u], o);
            }
            #pragma unroll
            for (int u = 0; u < PPW; ++u) {
                if (g[u] != 0.0f) {
                    float al = norms[p[u]], be = norms[q[u]];
                    float tau = (be - al) / (2.0f * g[u]);
                    float t = 1.0f / (fabsf(tau) + sqrtf(1.0f + tau * tau));
                    if (tau < 0.0f) t = -t;
                    float c = rsqrtf(1.0f + t * t);
                    float s = t * c;
                    float2 np, nq;
                    np.x = c * ap[u].x - s * aq[u].x;
                    np.y = c * ap[u].y - s * aq[u].y;
                    nq.x = s * ap[u].x + c * aq[u].x;
                    nq.y = s * ap[u].y + c * aq[u].y;
                    As2[p[u] * 33 + lane] = np;
                    As2[q[u] * 33 + lane] = nq;
                    if (lane == 0) {
                        float cc = c * c, ss = s * s, cs2 = 2.0f * c * s;
                        norms[p[u]] = cc * al - cs2 * g[u] + ss * be;
                        norms[q[u]] = ss * al + cs2 * g[u] + cc * be;
                    }
                }
            }
            __syncthreads();
        }
    }

    for (int j = wid; j < 64; j += NW) {
        float2 a = As2[j * 33 + lane];
        float s = a.x * a.x + a.y * a.y;
        #pragma unroll
        for (int o = 16; o; o >>= 1) s += __shfl_xor_sync(0xFFFFFFFFu, s, o);
        if (lane == 0) {
            s = fmaxf(s, 1e-30f);
            float lam = sqrtf(s) - shift_s;
            gv[j] = apply_fn(f1, lam) / s;
            if (f2 != F_NONE) gv2[j] = apply_fn(f2, lam) / s;
        }
    }
    __syncthreads();

    constexpr int TRI = MATSZ / TPB / 4;
    const int ti = (tid >> 4) * TRI;
    const int tj = (tid & 15) << 2;
    {
        float acc[TRI][4] = {};
        #pragma unroll 4
        for (int k = 0; k < 64; ++k) {
            const float* ck = Asf + k * 66;
            float gk = gv[k];
            float a[TRI], b[4];
            #pragma unroll
            for (int r = 0; r < TRI; ++r) a[r] = gk * ck[ti + r];
            #pragma unroll
            for (int c = 0; c < 4; ++c) b[c] = ck[tj + c];
            #pragma unroll
            for (int r = 0; r < TRI; ++r)
                #pragma unroll
                for (int c = 0; c < 4; ++c) acc[r][c] += a[r] * b[c];
        }
        #pragma unroll
        for (int r = 0; r < TRI; ++r) {
            float4 v = make_float4(acc[r][0], acc[r][1], acc[r][2], acc[r][3]);
            *reinterpret_cast<float4*>(out1 + boff + (size_t)(ti + r) * 64 + tj) = v;
        }
    }
    if (f2 != F_NONE) {
        float acc[TRI][4] = {};
        #pragma unroll 4
        for (int k = 0; k < 64; ++k) {
            const float* ck = Asf + k * 66;
            float gk = gv2[k];
            float a[TRI], b[4];
            #pragma unroll
            for (int r = 0; r < TRI; ++r) a[r] = gk * ck[ti + r];
            #pragma unroll
            for (int c = 0; c < 4; ++c) b[c] = ck[tj + c];
            #pragma unroll
            for (int r = 0; r < TRI; ++r)
                #pragma unroll
                for (int c = 0; c < 4; ++c) acc[r][c] += a[r] * b[c];
        }
        #pragma unroll
        for (int r = 0; r < TRI; ++r) {
            float4 v = make_float4(acc[r][0], acc[r][1], acc[r][2], acc[r][3]);
            *reinterpret_cast<float4*>(out2 + boff + (size_t)(ti + r) * 64 + tj) = v;
        }
    }
}

// 4x4 register tile inner product: C[ti..][tj..] += op(A) op(B)
template <int TA, int TB>
__device__ __forceinline__ void tile_mm(const float* __restrict__ A,
                                        const float* __restrict__ B,
                                        float acc[4][4], int ti, int tj)
{
    #pragma unroll 4
    for (int k = 0; k < 64; ++k) {
        float a[4], b[4];
        #pragma unroll
        for (int r = 0; r < 4; ++r) a[r] = TA ? A[k * 64 + ti + r] : A[(ti + r) * 64 + k];
        #pragma unroll
        for (int c = 0; c < 4; ++c) b[c] = TB ? B[(tj + c) * 64 + k] : B[k * 64 + tj + c];
        #pragma unroll
        for (int r = 0; r < 4; ++r)
            #pragma unroll
            for (int c = 0; c < 4; ++c) acc[r][c] += a[r] * b[c];
    }
}

// out_b = scale * L @ X_b @ op(R)  (L, R broadcast)
__global__ __launch_bounds__(256) void cong_kernel(
    const float* __restrict__ Lm, const float* __restrict__ Xb,
    const float* __restrict__ Rm, float* __restrict__ out,
    int useScale, int transR)
{
    __shared__ float Ls[MATSZ], Rs[MATSZ], Xs[MATSZ];
    const int tid = threadIdx.x;
    const size_t boff = (size_t)blockIdx.x * MATSZ;
    for (int i = tid; i < MATSZ; i += 256) {
        Ls[i] = Lm[i]; Rs[i] = Rm[i]; Xs[i] = Xb[boff + i];
    }
    __syncthreads();

    const int ti = (tid >> 4) << 2, tj = (tid & 15) << 2;
    float acc[4][4] = {};
    tile_mm<0, 0>(Ls, Xs, acc, ti, tj);
    __syncthreads();
    #pragma unroll
    for (int r = 0; r < 4; ++r)
        #pragma unroll
        for (int c = 0; c < 4; ++c) Xs[(ti + r) * 64 + tj + c] = acc[r][c];
    __syncthreads();

    float sc = useScale ? g_scal[0] : 1.0f;
    float acc2[4][4] = {};
    if (transR) tile_mm<0, 1>(Xs, Rs, acc2, ti, tj);
    else        tile_mm<0, 0>(Xs, Rs, acc2, ti, tj);
    #pragma unroll
    for (int r = 0; r < 4; ++r) {
        float4 v = make_float4(acc2[r][0] * sc, acc2[r][1] * sc,
                               acc2[r][2] * sc, acc2[r][3] * sc);
        *reinterpret_cast<float4*>(out + boff + (size_t)(ti + r) * 64 + tj) = v;
    }
}

// out_b = A_b @ B_(b*strideB)   (strideB = 0 broadcasts B)
__global__ __launch_bounds__(256) void gemmB_kernel(
    const float* __restrict__ A, const float* __restrict__ Bm, int strideB,
    float* __restrict__ out)
{
    __shared__ float As_[MATSZ], Bs_[MATSZ];
    const int tid = threadIdx.x;
    const size_t boff = (size_t)blockIdx.x * MATSZ;
    const float* Bb = Bm + (size_t)blockIdx.x * strideB;
    for (int i = tid; i < MATSZ; i += 256) { As_[i] = A[boff + i]; Bs_[i] = Bb[i]; }
    __syncthreads();
    const int ti = (tid >> 4) << 2, tj = (tid & 15) << 2;
    float acc[4][4] = {};
    tile_mm<0, 0>(As_, Bs_, acc, ti, tj);
    #pragma unroll
    for (int r = 0; r < 4; ++r) {
        float4 v = make_float4(acc[r][0], acc[r][1], acc[r][2], acc[r][3]);
        *reinterpret_cast<float4*>(out + boff + (size_t)(ti + r) * 64 + tj) = v;
    }
}

// single 64x64 gemm: C = op(A) @ B
__global__ __launch_bounds__(256) void gemm1_kernel(
    const float* __restrict__ A, const float* __restrict__ B,
    float* __restrict__ C, int transA)
{
    __shared__ float As_[MATSZ], Bs_[MATSZ];
    const int tid = threadIdx.x;
    for (int i = tid; i < MATSZ; i += 256) { As_[i] = A[i]; Bs_[i] = B[i]; }
    __syncthreads();
    const int ti = (tid >> 4) << 2, tj = (tid & 15) << 2;
    float acc[4][4] = {};
    if (transA) tile_mm<1, 0>(As_, Bs_, acc, ti, tj);
    else        tile_mm<0, 0>(As_, Bs_, acc, ti, tj);
    #pragma unroll
    for (int r = 0; r < 4; ++r) {
        float4 v = make_float4(acc[r][0], acc[r][1], acc[r][2], acc[r][3]);
        *reinterpret_cast<float4*>(C + (size_t)(ti + r) * 64 + tj) = v;
    }
}

// out[e] = mean_b in[b*4096 + e]
__global__ void mean_kernel(const float* __restrict__ in, float* __restrict__ out)
{
    int e = blockIdx.x * blockDim.x + threadIdx.x;
    double a0 = 0, a1 = 0, a2 = 0, a3 = 0;
    for (int b = 0; b < NB; b += 4) {
        a0 += (double)in[(size_t)(b + 0) * MATSZ + e];
        a1 += (double)in[(size_t)(b + 1) * MATSZ + e];
        a2 += (double)in[(size_t)(b + 2) * MATSZ + e];
        a3 += (double)in[(size_t)(b + 3) * MATSZ + e];
    }
    out[e] = (float)((a0 + a1 + a2 + a3) * (1.0 / (double)NB));
}

// deterministic two-pass sum of squares
__global__ __launch_bounds__(256) void sumsq_kernel(const float* __restrict__ in)
{
    __shared__ double sh[256];
    const int tid = threadIdx.x;
    const size_t base = (size_t)blockIdx.x * 65536;
    double a = 0;
    for (int i = tid; i < 65536; i += 256) {
        float v = in[base + i];
        a += (double)v * (double)v;
    }
    sh[tid] = a;
    __syncthreads();
    for (int s = 128; s > 0; s >>= 1) {
        if (tid < s) sh[tid] += sh[tid + s];
        __syncthreads();
    }
    if (tid == 0) g_part[blockIdx.x] = sh[0];
}

__global__ void finalize_kernel(const float* __restrict__ shift)
{
    __shared__ double sh[256];
    const int tid = threadIdx.x;
    sh[tid] = g_part[tid];
    __syncthreads();
    for (int s = 128; s > 0; s >>= 1) {
        if (tid < s) sh[tid] += sh[tid + s];
        __syncthreads();
    }
    if (tid == 0) {
        double var = sh[0] / (double)NB;
        g_scal[0] = shift[0] / (float)sqrt(var + 1e-5);
    }
}

extern "C" void kernel_launch(void* const* d_in, const int* in_sizes, int n_in,
                              void* d_out, int out_size)
{
    const float* X     = (const float*)d_in[0];
    const float* W     = (const float*)d_in[1];
    const float* M     = (const float*)d_in[2];
    const float* shift = (const float*)d_in[3];
    float* out = (float*)d_out;

    float *bufA, *bufB, *bufC, *bufD, *sm;
    cudaGetSymbolAddress((void**)&bufA, g_bufA);
    cudaGetSymbolAddress((void**)&bufB, g_bufB);
    cudaGetSymbolAddress((void**)&bufC, g_bufC);
    cudaGetSymbolAddress((void**)&bufD, g_bufD);
    cudaGetSymbolAddress((void**)&sm,   g_small);

    cudaFuncSetAttribute(nssqrt_kernel, cudaFuncAttributeMaxDynamicSharedMemorySize, 65536);
    cudaFuncSetAttribute(expm_kernel,   cudaFuncAttributeMaxDynamicSharedMemorySize, 49152);

    #define SLOT(i) (sm + (i) * MATSZ)
    // slots: 0 Mh, 1 Mnh, 2 Wh, 3 tmp, 4 Wc, 5 Wch, 6 Wcnh, 7 P, 8 Q, 9 R,
    //        10 G0, 11 G0h, 12 G0nh, 13 Tm, 14 expTm, 15 G, 16 mnh

    // parameter prep (tiny single-matrix ops; 8 sweeps, negligible cost)
    jac1s<1024><<<1, 1024>>>(M, SLOT(0), SLOT(1), F_SQRT, F_INVSQRT, 0, 8);   // Mh, Mnh
    jac1s<1024><<<1, 1024>>>(W, SLOT(2), SLOT(2), F_SQRT, F_NONE, 0, 8);      // Wh
    gemm1_kernel<<<1, 256>>>(SLOT(1), SLOT(2), SLOT(3), 0);                   // Mnh Wh
    gemm1_kernel<<<1, 256>>>(SLOT(3), SLOT(1), SLOT(4), 0);                   // Wc
    jac1s<1024><<<1, 1024>>>(SLOT(4), SLOT(5), SLOT(6), F_SQRT, F_INVSQRT, 0, 8); // Wch, Wcnh
    gemm1_kernel<<<1, 256>>>(SLOT(6), SLOT(2), SLOT(7), 0);                   // P = Wcnh Wh
    gemm1_kernel<<<1, 256>>>(SLOT(0), SLOT(5), SLOT(8), 0);                   // Q = Mh Wch
    gemm1_kernel<<<1, 256>>>(SLOT(8), SLOT(8), SLOT(9), 1);                   // R = Q^T Q

    // Xp = X^{1/2} (Newton-Schulz); Xc = Mnh Xp Mnh
    nssqrt_kernel<<<NB, 256, 65536>>>(X, bufA);
    cong_kernel<<<NB, 256>>>(SLOT(1), bufA, SLOT(1), bufB, 0, 0);             // Xc

    // bary_geom: 1 Karcher step from arithmetic mean
    mean_kernel<<<16, 256>>>(bufB, SLOT(10));                                 // G0
    jac1s<1024><<<1, 1024>>>(SLOT(10), SLOT(11), SLOT(12), F_SQRT, F_INVSQRT, 0, 8);
    cong_kernel<<<NB, 256>>>(SLOT(12), bufB, SLOT(12), bufC, 0, 0);
    jac1s<512><<<NB, 512>>>(bufC, bufA, bufA, F_LOG, F_NONE, 0, 7);
    mean_kernel<<<16, 256>>>(bufA, SLOT(13));                                 // Tm
    jac1s<1024><<<1, 1024>>>(SLOT(13), SLOT(14), SLOT(14), F_EXP, F_NONE, 1, 8); // exp (shift)
    gemm1_kernel<<<1, 256>>>(SLOT(11), SLOT(14), SLOT(3), 0);
    gemm1_kernel<<<1, 256>>>(SLOT(3), SLOT(11), SLOT(15), 0);                 // G
    jac1s<1024><<<1, 1024>>>(SLOT(15), SLOT(16), SLOT(16), F_INVSQRT, F_NONE, 0, 8); // mnh

    // tangent at I, variance, scale
    cong_kernel<<<NB, 256>>>(SLOT(16), bufB, SLOT(16), bufC, 0, 0);
    jac1s<512><<<NB, 512>>>(bufC, bufD, bufD, F_LOG, F_NONE, 0, 7);           // T0
    sumsq_kernel<<<256, 256>>>(bufD);
    finalize_kernel<<<1, 256>>>(shift);

    // arg = factor * P T0 P^T ; E = exp(arg) (scaling & squaring)
    cong_kernel<<<NB, 256>>>(SLOT(7), bufD, SLOT(7), bufC, 1, 1);
    expm_kernel<<<NB, 256, 49152>>>(bufC, bufA);                              // E

    // out = Q (E R E) Q^T
    gemmB_kernel<<<NB, 256>>>(bufA, SLOT(9), 0, bufC);                        // E R
    gemmB_kernel<<<NB, 256>>>(bufC, bufA, MATSZ, bufD);                       // (E R) E
    cong_kernel<<<NB, 256>>>(SLOT(8), bufD, SLOT(8), out, 0, 1);
    #undef SLOT
}